// round 12
// baseline (speedup 1.0000x reference)
#include <cuda_runtime.h>
#include <cuda_fp16.h>
#include <cstdint>

#define NIMG 64
#define CCH 256
#define NCHUNK 16            // 16 cins per chunk
#define STAGE 52992          // A 38912 + B 14080
#define NSTAGE 4
#define SMEM_BYTES (NSTAGE*STAGE)   // 211968
#define NTHR 512

// ---- scratch (__device__ globals; no allocation) ----
__device__ __half2 g_x16[(size_t)NIMG*128*1024];   // packed: [img][cpair][pix] = {c2i, c2i+1}
__device__ __half2 g_h16[(size_t)NIMG*128*1024];   // intermediate h, same layout
__device__ __half  g_w1h[(size_t)CCH*2304];        // k' = chunk*144 + off*16 + ci
__device__ __half  g_w2h[(size_t)CCH*2304];
__device__ float   g_inv [2][CCH];
__device__ float   g_bias[2][CCH];

__global__ void bn_prep_kernel(const float* __restrict__ g1, const float* __restrict__ b1,
                               const float* __restrict__ rm1, const float* __restrict__ rv1,
                               const float* __restrict__ g2, const float* __restrict__ b2,
                               const float* __restrict__ rm2, const float* __restrict__ rv2){
    int i = threadIdx.x;
    if (i < CCH){
        float i1 = g1[i]*rsqrtf(rv1[i]+1e-5f);
        g_inv[0][i]=i1; g_bias[0][i]=b1[i]-rm1[i]*i1;
        float i2 = g2[i]*rsqrtf(rv2[i]+1e-5f);
        g_inv[1][i]=i2; g_bias[1][i]=b2[i]-rm2[i]*i2;
    }
}

// x fp32 NCHW -> packed channel-pair fp16
__global__ void pack_x_kernel(const float* __restrict__ x){
    int i = blockIdx.x*blockDim.x + threadIdx.x;        // 32768*256 exact
    int pix = i & 1023, pr = (i >> 10) & 127, img = i >> 17;
    size_t b = ((size_t)(img*256 + 2*pr))*1024 + pix;
    g_x16[i] = __floats2half2_rn(x[b], x[b + 1024]);
}

// W[co][cin][3][3] -> fp16 Wt[co][chunk*144 + off*16 + ci],  cin = chunk*16+ci
__global__ void wtrans_kernel(const float* __restrict__ w1, const float* __restrict__ w2){
    int i = blockIdx.x*blockDim.x + threadIdx.x;        // 2304*256 exact
    int co = i / 2304, k = i - co*2304;
    int chunk = k / 144, r = k - chunk*144, off = r >> 4, ci = r & 15;
    int src = co*2304 + (chunk*16 + ci)*9 + off;
    g_w1h[i] = __float2half_rn(w1[src]);
    g_w2h[i] = __float2half_rn(w2[src]);
}

// ---- PTX helpers ----
__device__ __forceinline__ void cp16(uint32_t d, const void* g){
    asm volatile("cp.async.cg.shared.global [%0], [%1], 16;\n" :: "r"(d), "l"(g));
}
__device__ __forceinline__ void cp16z(uint32_t d, const void* g, int ok){
    int sz = ok ? 16 : 0;
    asm volatile("cp.async.cg.shared.global [%0], [%1], 16, %2;\n" :: "r"(d), "l"(g), "r"(sz));
}
__device__ __forceinline__ void ldsm4(uint32_t* r, uint32_t a){
    asm volatile("ldmatrix.sync.aligned.m8n8.x4.shared.b16 {%0,%1,%2,%3}, [%4];"
                 : "=r"(r[0]), "=r"(r[1]), "=r"(r[2]), "=r"(r[3]) : "r"(a));
}
__device__ __forceinline__ uint32_t lds32(uint32_t a){
    uint32_t v; asm volatile("ld.shared.b32 %0, [%1];" : "=r"(v) : "r"(a)); return v;
}
__device__ __forceinline__ void mma16(float* c, const uint32_t* a, const uint32_t* b){
    asm volatile("mma.sync.aligned.m16n8k16.row.col.f32.f16.f16.f32 "
        "{%0,%1,%2,%3}, {%4,%5,%6,%7}, {%8,%9}, {%0,%1,%2,%3};\n"
        : "+f"(c[0]), "+f"(c[1]), "+f"(c[2]), "+f"(c[3])
        : "r"(a[0]), "r"(a[1]), "r"(a[2]), "r"(a[3]), "r"(b[0]), "r"(b[1]));
}

// MODE 0: B = g_x16, out = g_h16 (BN1+ReLU, fp16 packed)
// MODE 1: B = g_h16, out = dout fp32 (BN2 + residual + ReLU)
template<int MODE>
__global__ __launch_bounds__(NTHR,1)
void conv_f16(const float* __restrict__ resid, float* __restrict__ dout){
    extern __shared__ char smem[];
    uint32_t sb = (uint32_t)__cvta_generic_to_shared(smem);
    const int tid = threadIdx.x, lane = tid & 31, warp = tid >> 5;
    const int qg = lane >> 2, qt = lane & 3, wm = warp & 1, wn = warp >> 1;  // wn 0..7
    const int bx = blockIdx.x, img = blockIdx.z, co0 = blockIdx.y*128, r0 = bx*8;

    const __half*  Wt   = (MODE==0) ? g_w1h : g_w2h;
    const __half2* Bsrc = (MODE==0) ? g_x16 : g_h16;

    // ---- pre-zero halo columns (u4 cols 7 and 40 of every B row, all stages) ----
    for (int z = tid; z < 640; z += NTHR){
        int s = z/160, r2 = z - s*160, pr = r2/20, r3 = r2 - pr*20, slot = r3 >> 1, side = r3 & 1;
        uint32_t ad = sb + (uint32_t)(s*STAGE + 38912 + (pr*440 + slot*44 + (side?40:7))*4);
        asm volatile("st.shared.u32 [%0], %1;" :: "r"(ad), "r"(0));
    }

    // ---- loader precompute (packed to keep reg pressure low) ----
    // A: 2304 16B ops/chunk -> j=0..3 all threads, j=4 for tid<256
    uint32_t a_rs[5];
    #pragma unroll
    for (int j = 0; j < 5; j++){
        int o = tid + j*NTHR;                 // < 2304 for valid entries
        int row = o/18, seg = o - row*18;
        a_rs[j] = ((uint32_t)row << 8) | (uint32_t)seg;
    }
    // B: 640 ops/chunk -> j=0 all threads, j=1 for tid<128
    uint32_t b_dst[2], b_off[2]; int b_ok[2];
    #pragma unroll
    for (int j = 0; j < 2; j++){
        int o = tid + j*NTHR;
        if (o < 640){
            int pr = o/80, rem = o - pr*80, slot = rem >> 3, seg = rem & 7;
            int gr = r0 + slot - 1;
            b_ok[j] = ((unsigned)gr < 32u) ? 1 : 0;
            b_dst[j] = (uint32_t)(38912 + pr*1760 + slot*176 + 32 + seg*16);
            b_off[j] = (uint32_t)((img*128 + pr)*1024 + (b_ok[j] ? gr : 0)*32 + seg*4); // half2 elems
        } else b_ok[j] = -1;
    }

    float acc[4][4][4];
    #pragma unroll
    for (int i=0;i<4;i++)
        #pragma unroll
        for (int j=0;j<4;j++)
            #pragma unroll
            for (int r=0;r<4;r++) acc[i][j][r] = 0.0f;

    auto LOAD = [&](int c){
        uint32_t s = sb + (uint32_t)((c & 3)*STAGE);
        #pragma unroll
        for (int j = 0; j < 5; j++){
            if (j < 4 || tid < 256){
                uint32_t row = a_rs[j] >> 8, seg = a_rs[j] & 255u;
                cp16(s + row*304 + seg*16, Wt + (co0 + row)*2304 + seg*8 + c*144);
            }
        }
        #pragma unroll
        for (int j = 0; j < 2; j++)
            if (b_ok[j] >= 0) cp16z(s + b_dst[j], Bsrc + b_off[j] + c*8192, b_ok[j]);
        asm volatile("cp.async.commit_group;\n");
    };

    LOAD(0); LOAD(1); LOAD(2);

    #pragma unroll 1
    for (int c = 0; c < NCHUNK; c++){
        if (c < NCHUNK-2)       asm volatile("cp.async.wait_group 2;\n");
        else if (c == NCHUNK-2) asm volatile("cp.async.wait_group 1;\n");
        else                    asm volatile("cp.async.wait_group 0;\n");
        __syncthreads();
        if (c + 3 < NCHUNK) LOAD(c+3);

        const uint32_t sA = sb + (uint32_t)((c & 3)*STAGE);
        const uint32_t sB = sA + 38912;
        #pragma unroll
        for (int off = 0; off < 9; off++){
            const int dh = off/3, dw = off - 3*(off/3);
            uint32_t a[4][4];
            #pragma unroll
            for (int mt = 0; mt < 4; mt++){
                uint32_t ad = sA + (uint32_t)((wm*64 + mt*16 + (lane & 15))*304
                                              + off*32 + ((lane >> 4) << 4));
                ldsm4(a[mt], ad);
            }
            uint32_t b[4][2];
            #pragma unroll
            for (int nt = 0; nt < 4; nt++){
                uint32_t ad = sB + (uint32_t)((qt*440 + (wn + dh)*44
                                               + 7 + nt*8 + dw + qg)*4);
                b[nt][0] = lds32(ad);
                b[nt][1] = lds32(ad + 7040);     // pair qt+4
            }
            #pragma unroll
            for (int mt = 0; mt < 4; mt++)
                #pragma unroll
                for (int nt = 0; nt < 4; nt++)
                    mma16(acc[mt][nt], a[mt], b[nt]);
        }
    }

    // ---------------- epilogue ----------------
    if (MODE == 0){
        __syncthreads();                       // stage smem still live on last chunks
        char* Sw = smem + warp*5120;           // per-warp staging [64 rows][40 halves]
        #pragma unroll
        for (int mt = 0; mt < 4; mt++){
            const int co = co0 + wm*64 + mt*16 + qg;
            const float i0 = g_inv[0][co],   s0 = g_bias[0][co];
            const float i1 = g_inv[0][co+8], s1 = g_bias[0][co+8];
            #pragma unroll
            for (int nt = 0; nt < 4; nt++){
                const int pxl = nt*8 + 2*qt;
                float v0 = fmaxf(fmaf(acc[mt][nt][0], i0, s0), 0.f);
                float v1 = fmaxf(fmaf(acc[mt][nt][1], i0, s0), 0.f);
                float v2 = fmaxf(fmaf(acc[mt][nt][2], i1, s1), 0.f);
                float v3 = fmaxf(fmaf(acc[mt][nt][3], i1, s1), 0.f);
                *(__half2*)(Sw + ((mt*16 + qg    )*40 + pxl)*2) = __floats2half2_rn(v0, v1);
                *(__half2*)(Sw + ((mt*16 + qg + 8)*40 + pxl)*2) = __floats2half2_rn(v2, v3);
            }
        }
        __syncwarp();
        #pragma unroll
        for (int it = 0; it < 8; it++){
            const int cpl = it*4 + (lane >> 3), px4 = lane & 7;   // cpl 0..31, 4 px each
            uint2 lo = *(uint2*)(Sw + ((2*cpl    )*40 + px4*4)*2);
            uint2 hi = *(uint2*)(Sw + ((2*cpl + 1)*40 + px4*4)*2);
            uint4 v;
            v.x = __byte_perm(lo.x, hi.x, 0x5410);
            v.y = __byte_perm(lo.x, hi.x, 0x7632);
            v.z = __byte_perm(lo.y, hi.y, 0x5410);
            v.w = __byte_perm(lo.y, hi.y, 0x7632);
            size_t idx = ((size_t)(img*128 + (co0 >> 1) + wm*32 + cpl))*1024
                       + bx*256 + wn*32 + px4*4;
            *(uint4*)((uint32_t*)g_h16 + idx) = v;
        }
    } else {
        #pragma unroll
        for (int mt = 0; mt < 4; mt++){
            const int co = co0 + wm*64 + mt*16 + qg;
            const float i0 = g_inv[1][co],   s0 = g_bias[1][co];
            const float i1 = g_inv[1][co+8], s1 = g_bias[1][co+8];
            #pragma unroll
            for (int nt = 0; nt < 4; nt++){
                const int p = bx*256 + wn*32 + nt*8 + 2*qt;
                const size_t o0 = ((size_t)(img*256 + co))*1024 + p;
                const size_t o1 = o0 + 8*1024;
                const float2 r0 = *(const float2*)(resid + o0);
                const float2 r1 = *(const float2*)(resid + o1);
                float2 w0, w1;
                w0.x = fmaxf(fmaf(acc[mt][nt][0], i0, s0) + r0.x, 0.f);
                w0.y = fmaxf(fmaf(acc[mt][nt][1], i0, s0) + r0.y, 0.f);
                w1.x = fmaxf(fmaf(acc[mt][nt][2], i1, s1) + r1.x, 0.f);
                w1.y = fmaxf(fmaf(acc[mt][nt][3], i1, s1) + r1.y, 0.f);
                *(float2*)(dout + o0) = w0;
                *(float2*)(dout + o1) = w1;
            }
        }
    }
}

extern "C" void kernel_launch(void* const* d_in, const int* in_sizes, int n_in,
                              void* d_out, int out_size){
    const float* x   = (const float*)d_in[0];
    const float* w1  = (const float*)d_in[1];
    const float* g1  = (const float*)d_in[2];
    const float* b1  = (const float*)d_in[3];
    const float* rm1 = (const float*)d_in[4];
    const float* rv1 = (const float*)d_in[5];
    const float* w2  = (const float*)d_in[6];
    const float* g2  = (const float*)d_in[7];
    const float* b2  = (const float*)d_in[8];
    const float* rm2 = (const float*)d_in[9];
    const float* rv2 = (const float*)d_in[10];
    float* out = (float*)d_out;

    bn_prep_kernel<<<1, 256>>>(g1,b1,rm1,rv1,g2,b2,rm2,rv2);
    pack_x_kernel<<<32768, 256>>>(x);
    wtrans_kernel<<<2304, 256>>>(w1, w2);

    cudaFuncSetAttribute(conv_f16<0>, cudaFuncAttributeMaxDynamicSharedMemorySize, SMEM_BYTES);
    cudaFuncSetAttribute(conv_f16<1>, cudaFuncAttributeMaxDynamicSharedMemorySize, SMEM_BYTES);
    dim3 grid(4, 2, NIMG);   // 512 CTAs
    conv_f16<0><<<grid, NTHR, SMEM_BYTES>>>(nullptr, nullptr);
    conv_f16<1><<<grid, NTHR, SMEM_BYTES>>>(x, out);
}

// round 15
// speedup vs baseline: 1.0434x; 1.0434x over previous
#include <cuda_runtime.h>
#include <cuda_fp16.h>
#include <cstdint>

#define NIMG 64
#define CCH 256
#define NTILE 1024          // (img 64) x (by 4) x (bx 4)
#define NCTA 148
#define STAGE 33536         // A 19456 + B 14080
#define OFF_BST 19456
#define OFF_STG 134144      // 4*STAGE
#define SMEM_BYTES 175104   // OFF_STG + 8*5120
#define NTHR 256

// ---- scratch (__device__ globals; no allocation) ----
__device__ __half2 g_x16[(size_t)NIMG*128*1024];   // packed: [img][cpair][pix]
__device__ __half2 g_h16[(size_t)NIMG*128*1024];   // intermediate h, same layout
__device__ __half  g_w1h[(size_t)CCH*2304];        // k' = chunk*144 + off*16 + ci
__device__ __half  g_w2h[(size_t)CCH*2304];
__device__ float   g_inv [2][CCH];
__device__ float   g_bias[2][CCH];

__device__ __forceinline__ uint32_t pack_h2(float lo, float hi){
    __half2 h = __floats2half2_rn(lo, hi);
    __half2_raw r = *(__half2_raw*)&h;
    return (uint32_t)r.x | ((uint32_t)r.y << 16);
}

// fused: weight transpose + BN fold
__global__ void prep_kernel(const float* __restrict__ w1, const float* __restrict__ w2,
                            const float* __restrict__ g1, const float* __restrict__ b1,
                            const float* __restrict__ rm1, const float* __restrict__ rv1,
                            const float* __restrict__ g2, const float* __restrict__ b2,
                            const float* __restrict__ rm2, const float* __restrict__ rv2){
    int i = blockIdx.x*blockDim.x + threadIdx.x;        // 2304*256 exact
    int co = i / 2304, k = i - co*2304;
    int chunk = k / 144, r = k - chunk*144, off = r >> 4, ci = r & 15;
    int src = co*2304 + (chunk*16 + ci)*9 + off;
    g_w1h[i] = __float2half_rn(w1[src]);
    g_w2h[i] = __float2half_rn(w2[src]);
    if (blockIdx.x == 0 && threadIdx.x < CCH){
        int t = threadIdx.x;
        float i1 = g1[t]*rsqrtf(rv1[t]+1e-5f);
        g_inv[0][t]=i1; g_bias[0][t]=b1[t]-rm1[t]*i1;
        float i2 = g2[t]*rsqrtf(rv2[t]+1e-5f);
        g_inv[1][t]=i2; g_bias[1][t]=b2[t]-rm2[t]*i2;
    }
}

// x fp32 NCHW -> packed channel-pair fp16, 4 px per thread
__global__ void pack_x_kernel(const float4* __restrict__ x4){
    int i = blockIdx.x*blockDim.x + threadIdx.x;        // 8192*256 exact
    int p4 = i & 255, pr = (i >> 8) & 127, img = i >> 15;
    size_t b = ((size_t)(img*256 + 2*pr))*256 + p4;     // float4 units
    float4 a = x4[b], c = x4[b + 256];
    uint4 v;
    v.x = pack_h2(a.x, c.x);
    v.y = pack_h2(a.y, c.y);
    v.z = pack_h2(a.z, c.z);
    v.w = pack_h2(a.w, c.w);
    *((uint4*)g_x16 + ((size_t)(img*128 + pr)*256 + p4)) = v;
}

// ---- PTX helpers ----
__device__ __forceinline__ void cp16(uint32_t d, const void* g){
    asm volatile("cp.async.cg.shared.global [%0], [%1], 16;\n" :: "r"(d), "l"(g));
}
__device__ __forceinline__ void cp16z(uint32_t d, const void* g, int ok){
    int sz = ok ? 16 : 0;
    asm volatile("cp.async.cg.shared.global [%0], [%1], 16, %2;\n" :: "r"(d), "l"(g), "r"(sz));
}
__device__ __forceinline__ void ldsm4(uint32_t* r, uint32_t a){
    asm volatile("ldmatrix.sync.aligned.m8n8.x4.shared.b16 {%0,%1,%2,%3}, [%4];"
                 : "=r"(r[0]), "=r"(r[1]), "=r"(r[2]), "=r"(r[3]) : "r"(a));
}
__device__ __forceinline__ uint32_t lds32(uint32_t a){
    uint32_t v; asm volatile("ld.shared.b32 %0, [%1];" : "=r"(v) : "r"(a)); return v;
}
__device__ __forceinline__ void mma16(float* c, const uint32_t* a, const uint32_t* b){
    asm volatile("mma.sync.aligned.m16n8k16.row.col.f32.f16.f16.f32 "
        "{%0,%1,%2,%3}, {%4,%5,%6,%7}, {%8,%9}, {%0,%1,%2,%3};\n"
        : "+f"(c[0]), "+f"(c[1]), "+f"(c[2]), "+f"(c[3])
        : "r"(a[0]), "r"(a[1]), "r"(a[2]), "r"(a[3]), "r"(b[0]), "r"(b[1]));
}

// persistent conv: each CTA walks tiles cta, cta+148, ... of 1024
// tile t: img=t>>4, by=(t>>2)&3 (co0=by*64), bx=t&3 (px rows r0=bx*8)
// MODE 0: B = g_x16, out = g_h16 (BN1+ReLU fp16 packed); MODE 1: out fp32 + residual
template<int MODE>
__global__ __launch_bounds__(NTHR,1)
void conv_f16(const float* __restrict__ resid, float* __restrict__ dout){
    extern __shared__ char smem[];
    uint32_t sb = (uint32_t)__cvta_generic_to_shared(smem);
    const int tid = threadIdx.x, lane = tid & 31, warp = tid >> 5;
    const int qg = lane >> 2, qt = lane & 3, wn = warp;       // 8 warps along N
    const int cta = blockIdx.x;

    const __half*  Wt   = (MODE==0) ? g_w1h : g_w2h;
    const __half2* Bsrc = (MODE==0) ? g_x16 : g_h16;

    // ---- zero halo columns once (words 7 and 40 of each 44-word B row, 4 stages) ----
    for (int z = tid; z < 640; z += NTHR){
        int s = z/160, r2 = z - s*160, pr = r2/20, r3 = r2 - pr*20, slot = r3 >> 1, side = r3 & 1;
        uint32_t ad = sb + (uint32_t)(s*STAGE + OFF_BST + (pr*440 + slot*44 + (side?40:7))*4);
        asm volatile("st.shared.u32 [%0], %1;" :: "r"(ad), "r"(0));
    }

    // ---- loader precompute ----
    // A: 1152 16B ops/chunk -> j=0..3 all, j=4 for tid<128
    uint32_t a_rs[5];
    #pragma unroll
    for (int j = 0; j < 5; j++){
        int o = tid + j*NTHR;
        int row = o/18, seg = o - row*18;
        a_rs[j] = ((uint32_t)row << 8) | (uint32_t)seg;
    }
    // B: 640 ops/chunk -> j=0,1 all threads, j=2 for tid<128
    uint32_t b_ps[3];
    #pragma unroll
    for (int j = 0; j < 3; j++){
        int o = tid + j*NTHR;
        if (o >= 640) o = 0;                 // unused slot (guarded at issue)
        int pr = o/80, rem = o - pr*80, slot = rem >> 3, seg = rem & 7;
        b_ps[j] = ((uint32_t)pr << 16) | ((uint32_t)slot << 8) | (uint32_t)seg;
    }

    int ntile = 0;
    for (int t = cta; t < NTILE; t += NCTA) ntile++;
    const int tot = ntile*16;

    auto LOAD = [&](int gl){
        const int c = gl & 15;
        const int tile = cta + (gl >> 4)*NCTA;
        const int img = tile >> 4, by = (tile >> 2) & 3, bx = tile & 3;
        const int co0 = by*64;
        uint32_t s = sb + (uint32_t)((gl & 3)*STAGE);
        #pragma unroll
        for (int j = 0; j < 5; j++){
            if (j < 4 || tid < 128){
                uint32_t row = a_rs[j] >> 8, seg = a_rs[j] & 255u;
                cp16(s + row*304 + seg*16, Wt + (co0 + row)*2304 + seg*8 + c*144);
            }
        }
        #pragma unroll
        for (int j = 0; j < 3; j++){
            if (j < 2 || tid < 128){         // 256+256+128 = 640 ops exactly
                uint32_t pr = b_ps[j] >> 16, slot = (b_ps[j] >> 8) & 255u, seg = b_ps[j] & 255u;
                int gr = bx*8 + (int)slot - 1;
                int ok = ((unsigned)gr < 32u) ? 1 : 0;
                uint32_t dst = s + OFF_BST + pr*1760 + slot*176 + 32 + seg*16;
                const __half2* src = Bsrc + ((size_t)(img*128 + c*8 + pr)*1024
                                             + (ok ? gr : 0)*32 + seg*4);
                cp16z(dst, src, ok);
            }
        }
        asm volatile("cp.async.commit_group;\n");
    };

    float acc[4][4][4];
    #pragma unroll
    for (int i=0;i<4;i++)
        #pragma unroll
        for (int j=0;j<4;j++)
            #pragma unroll
            for (int r=0;r<4;r++) acc[i][j][r] = 0.0f;

    LOAD(0); LOAD(1); LOAD(2);

    #pragma unroll 1
    for (int gl = 0; gl < tot; gl++){
        if (gl <= tot-3)       asm volatile("cp.async.wait_group 2;\n");
        else if (gl == tot-2)  asm volatile("cp.async.wait_group 1;\n");
        else                   asm volatile("cp.async.wait_group 0;\n");
        __syncthreads();
        if (gl + 3 < tot) LOAD(gl + 3);

        const uint32_t sA = sb + (uint32_t)((gl & 3)*STAGE);
        const uint32_t sB = sA + OFF_BST;
        #pragma unroll
        for (int off = 0; off < 9; off++){
            const int dh = off/3, dw = off - 3*(off/3);
            uint32_t a[4][4];
            #pragma unroll
            for (int mt = 0; mt < 4; mt++){
                uint32_t ad = sA + (uint32_t)((mt*16 + (lane & 15))*304
                                              + off*32 + ((lane >> 4) << 4));
                ldsm4(a[mt], ad);
            }
            uint32_t b[4][2];
            #pragma unroll
            for (int nt = 0; nt < 4; nt++){
                uint32_t ad = sB + (uint32_t)((qt*440 + (wn + dh)*44
                                               + 7 + nt*8 + dw + qg)*4);
                b[nt][0] = lds32(ad);
                b[nt][1] = lds32(ad + 7040);     // cpair qt+4
            }
            #pragma unroll
            for (int mt = 0; mt < 4; mt++)
                #pragma unroll
                for (int nt = 0; nt < 4; nt++)
                    mma16(acc[mt][nt], a[mt], b[nt]);
        }

        // ---- tile finished: fused epilogue (own staging smem; overlaps next loads) ----
        if ((gl & 15) == 15){
            const int tile = cta + (gl >> 4)*NCTA;
            const int img = tile >> 4, by = (tile >> 2) & 3, bx = tile & 3;
            const int co0 = by*64;
            if (MODE == 0){
                char* Sw = smem + OFF_STG + warp*5120;   // [64 rows][40 halves]
                #pragma unroll
                for (int mt = 0; mt < 4; mt++){
                    const int co = co0 + mt*16 + qg;
                    const float i0 = g_inv[0][co],   s0 = g_bias[0][co];
                    const float i1 = g_inv[0][co+8], s1 = g_bias[0][co+8];
                    #pragma unroll
                    for (int nt = 0; nt < 4; nt++){
                        const int pxl = nt*8 + 2*qt;
                        float v0 = fmaxf(fmaf(acc[mt][nt][0], i0, s0), 0.f);
                        float v1 = fmaxf(fmaf(acc[mt][nt][1], i0, s0), 0.f);
                        float v2 = fmaxf(fmaf(acc[mt][nt][2], i1, s1), 0.f);
                        float v3 = fmaxf(fmaf(acc[mt][nt][3], i1, s1), 0.f);
                        *(uint32_t*)(Sw + ((mt*16 + qg    )*40 + pxl)*2) = pack_h2(v0, v1);
                        *(uint32_t*)(Sw + ((mt*16 + qg + 8)*40 + pxl)*2) = pack_h2(v2, v3);
                    }
                }
                __syncwarp();
                #pragma unroll
                for (int it = 0; it < 8; it++){
                    const int cpl = it*4 + (lane >> 3), px4 = lane & 7;
                    uint2 lo = *(uint2*)(Sw + ((2*cpl    )*40 + px4*4)*2);
                    uint2 hi = *(uint2*)(Sw + ((2*cpl + 1)*40 + px4*4)*2);
                    uint4 v;
                    v.x = __byte_perm(lo.x, hi.x, 0x5410);
                    v.y = __byte_perm(lo.x, hi.x, 0x7632);
                    v.z = __byte_perm(lo.y, hi.y, 0x5410);
                    v.w = __byte_perm(lo.y, hi.y, 0x7632);
                    size_t idx = ((size_t)(img*128 + by*32 + cpl))*1024
                               + bx*256 + wn*32 + px4*4;
                    *(uint4*)((uint32_t*)g_h16 + idx) = v;
                }
                __syncwarp();
            } else {
                #pragma unroll
                for (int mt = 0; mt < 4; mt++){
                    const int co = co0 + mt*16 + qg;
                    const float i0 = g_inv[1][co],   s0 = g_bias[1][co];
                    const float i1 = g_inv[1][co+8], s1 = g_bias[1][co+8];
                    #pragma unroll
                    for (int nt = 0; nt < 4; nt++){
                        const int p = bx*256 + wn*32 + nt*8 + 2*qt;
                        const size_t o0 = ((size_t)(img*256 + co))*1024 + p;
                        const size_t o1 = o0 + 8*1024;
                        const float2 r0 = *(const float2*)(resid + o0);
                        const float2 r1 = *(const float2*)(resid + o1);
                        float2 w0, w1;
                        w0.x = fmaxf(fmaf(acc[mt][nt][0], i0, s0) + r0.x, 0.f);
                        w0.y = fmaxf(fmaf(acc[mt][nt][1], i0, s0) + r0.y, 0.f);
                        w1.x = fmaxf(fmaf(acc[mt][nt][2], i1, s1) + r1.x, 0.f);
                        w1.y = fmaxf(fmaf(acc[mt][nt][3], i1, s1) + r1.y, 0.f);
                        *(float2*)(dout + o0) = w0;
                        *(float2*)(dout + o1) = w1;
                    }
                }
            }
            #pragma unroll
            for (int i=0;i<4;i++)
                #pragma unroll
                for (int j=0;j<4;j++)
                    #pragma unroll
                    for (int r=0;r<4;r++) acc[i][j][r] = 0.0f;
        }
    }
}

extern "C" void kernel_launch(void* const* d_in, const int* in_sizes, int n_in,
                              void* d_out, int out_size){
    const float* x   = (const float*)d_in[0];
    const float* w1  = (const float*)d_in[1];
    const float* g1  = (const float*)d_in[2];
    const float* b1  = (const float*)d_in[3];
    const float* rm1 = (const float*)d_in[4];
    const float* rv1 = (const float*)d_in[5];
    const float* w2  = (const float*)d_in[6];
    const float* g2  = (const float*)d_in[7];
    const float* b2  = (const float*)d_in[8];
    const float* rm2 = (const float*)d_in[9];
    const float* rv2 = (const float*)d_in[10];
    float* out = (float*)d_out;

    prep_kernel<<<2304, 256>>>(w1, w2, g1,b1,rm1,rv1, g2,b2,rm2,rv2);
    pack_x_kernel<<<8192, 256>>>((const float4*)x);

    cudaFuncSetAttribute(conv_f16<0>, cudaFuncAttributeMaxDynamicSharedMemorySize, SMEM_BYTES);
    cudaFuncSetAttribute(conv_f16<1>, cudaFuncAttributeMaxDynamicSharedMemorySize, SMEM_BYTES);
    conv_f16<0><<<NCTA, NTHR, SMEM_BYTES>>>(nullptr, nullptr);
    conv_f16<1><<<NCTA, NTHR, SMEM_BYTES>>>(x, out);
}

// round 17
// speedup vs baseline: 1.2633x; 1.2108x over previous
#include <cuda_runtime.h>
#include <cuda_fp16.h>
#include <cstdint>

#define NIMG 64
#define CCH 256
#define NTILE 1024          // (img 64) x (by 4) x (bx 4)
#define NCTA 148
#define STAGE 33536         // A 19456 + B 14080
#define OFF_BST 19456
#define OFF_STG 134144      // 4*STAGE
#define BAR_OFF 175104      // OFF_STG + 8*5120
#define SMEM_BYTES 175232
#define NTHR 256

// ---- scratch (__device__ globals; no allocation) ----
__device__ __half2 g_x16[(size_t)NIMG*128*1024];   // packed: [img][cpair][pix]
__device__ __half2 g_h16[(size_t)NIMG*128*1024];   // intermediate h, same layout
__device__ __half  g_w1h[(size_t)CCH*2304];        // k' = chunk*144 + off*16 + ci
__device__ __half  g_w2h[(size_t)CCH*2304];
__device__ float   g_inv [2][CCH];
__device__ float   g_bias[2][CCH];

__device__ __forceinline__ uint32_t pack_h2(float lo, float hi){
    __half2 h = __floats2half2_rn(lo, hi);
    __half2_raw r = *(__half2_raw*)&h;
    return (uint32_t)r.x | ((uint32_t)r.y << 16);
}

// fused: weight transpose + BN fold
__global__ void prep_kernel(const float* __restrict__ w1, const float* __restrict__ w2,
                            const float* __restrict__ g1, const float* __restrict__ b1,
                            const float* __restrict__ rm1, const float* __restrict__ rv1,
                            const float* __restrict__ g2, const float* __restrict__ b2,
                            const float* __restrict__ rm2, const float* __restrict__ rv2){
    int i = blockIdx.x*blockDim.x + threadIdx.x;        // 2304*256 exact
    int co = i / 2304, k = i - co*2304;
    int chunk = k / 144, r = k - chunk*144, off = r >> 4, ci = r & 15;
    int src = co*2304 + (chunk*16 + ci)*9 + off;
    g_w1h[i] = __float2half_rn(w1[src]);
    g_w2h[i] = __float2half_rn(w2[src]);
    if (blockIdx.x == 0 && threadIdx.x < CCH){
        int t = threadIdx.x;
        float i1 = g1[t]*rsqrtf(rv1[t]+1e-5f);
        g_inv[0][t]=i1; g_bias[0][t]=b1[t]-rm1[t]*i1;
        float i2 = g2[t]*rsqrtf(rv2[t]+1e-5f);
        g_inv[1][t]=i2; g_bias[1][t]=b2[t]-rm2[t]*i2;
    }
}

// x fp32 NCHW -> packed channel-pair fp16, 4 px per thread
__global__ void pack_x_kernel(const float4* __restrict__ x4){
    int i = blockIdx.x*blockDim.x + threadIdx.x;        // 8192*256 exact
    int p4 = i & 255, pr = (i >> 8) & 127, img = i >> 15;
    size_t b = ((size_t)(img*256 + 2*pr))*256 + p4;     // float4 units
    float4 a = x4[b], c = x4[b + 256];
    uint4 v;
    v.x = pack_h2(a.x, c.x);
    v.y = pack_h2(a.y, c.y);
    v.z = pack_h2(a.z, c.z);
    v.w = pack_h2(a.w, c.w);
    *((uint4*)g_x16 + ((size_t)(img*128 + pr)*256 + p4)) = v;
}

// ---- PTX helpers ----
__device__ __forceinline__ void cp16(uint32_t d, const void* g){
    asm volatile("cp.async.cg.shared.global [%0], [%1], 16;\n" :: "r"(d), "l"(g));
}
__device__ __forceinline__ void cp16z(uint32_t d, const void* g, int ok){
    int sz = ok ? 16 : 0;
    asm volatile("cp.async.cg.shared.global [%0], [%1], 16, %2;\n" :: "r"(d), "l"(g), "r"(sz));
}
__device__ __forceinline__ void mbinit(uint32_t a, uint32_t c){
    asm volatile("mbarrier.init.shared.b64 [%0], %1;" :: "r"(a), "r"(c) : "memory");
}
__device__ __forceinline__ void mbarrive(uint32_t a){
    asm volatile("mbarrier.arrive.shared.b64 _, [%0];" :: "r"(a) : "memory");
}
__device__ __forceinline__ void cp_arrive(uint32_t a){
    // .noinc: thread's completion counts against the init count (256)
    asm volatile("cp.async.mbarrier.arrive.noinc.shared.b64 [%0];" :: "r"(a) : "memory");
}
__device__ __forceinline__ void mwait(uint32_t mb, uint32_t par){
    uint32_t done;
    asm volatile("{\n\t.reg .pred p;\n\t"
                 "mbarrier.try_wait.parity.acquire.cta.shared::cta.b64 p, [%1], %2;\n\t"
                 "selp.b32 %0,1,0,p;\n\t}" : "=r"(done) : "r"(mb), "r"(par) : "memory");
    if (!done){
        asm volatile("{\n\t.reg .pred P1;\n\t"
                     "WL_%=:\n\t"
                     "mbarrier.try_wait.parity.acquire.cta.shared::cta.b64 P1, [%0], %1, 0x989680;\n\t"
                     "@P1 bra.uni WD_%=;\n\t"
                     "bra.uni WL_%=;\n\t"
                     "WD_%=:\n\t}" :: "r"(mb), "r"(par) : "memory");
    }
}
__device__ __forceinline__ void ldsm4(uint32_t* r, uint32_t a){
    asm volatile("ldmatrix.sync.aligned.m8n8.x4.shared.b16 {%0,%1,%2,%3}, [%4];"
                 : "=r"(r[0]), "=r"(r[1]), "=r"(r[2]), "=r"(r[3]) : "r"(a));
}
__device__ __forceinline__ uint32_t lds32(uint32_t a){
    uint32_t v; asm volatile("ld.shared.b32 %0, [%1];" : "=r"(v) : "r"(a)); return v;
}
__device__ __forceinline__ void mma16(float* c, const uint32_t* a, const uint32_t* b){
    asm volatile("mma.sync.aligned.m16n8k16.row.col.f32.f16.f16.f32 "
        "{%0,%1,%2,%3}, {%4,%5,%6,%7}, {%8,%9}, {%0,%1,%2,%3};\n"
        : "+f"(c[0]), "+f"(c[1]), "+f"(c[2]), "+f"(c[3])
        : "r"(a[0]), "r"(a[1]), "r"(a[2]), "r"(a[3]), "r"(b[0]), "r"(b[1]));
}

// persistent conv, mbarrier-paced per-warp pipeline (no block barriers in steady state)
// tile t: img=t>>4, by=(t>>2)&3 (co0=by*64), bx=t&3 (px rows r0=bx*8)
// MODE 0: B = g_x16, out = g_h16 (BN1+ReLU fp16 packed); MODE 1: out fp32 + residual
template<int MODE>
__global__ __launch_bounds__(NTHR,1)
void conv_f16(const float* __restrict__ resid, float* __restrict__ dout){
    extern __shared__ char smem[];
    uint32_t sb = (uint32_t)__cvta_generic_to_shared(smem);
    const int tid = threadIdx.x, lane = tid & 31, warp = tid >> 5;
    const int qg = lane >> 2, qt = lane & 3, wn = warp;       // 8 warps along N
    const int cta = blockIdx.x;
    const uint32_t FULLB = sb + BAR_OFF, EMPTB = sb + BAR_OFF + 32;

    const __half*  Wt   = (MODE==0) ? g_w1h : g_w2h;
    const __half2* Bsrc = (MODE==0) ? g_x16 : g_h16;

    // ---- one-time init: halo zeros + mbarriers ----
    for (int z = tid; z < 640; z += NTHR){
        int s = z/160, r2 = z - s*160, pr = r2/20, r3 = r2 - pr*20, slot = r3 >> 1, side = r3 & 1;
        uint32_t ad = sb + (uint32_t)(s*STAGE + OFF_BST + (pr*440 + slot*44 + (side?40:7))*4);
        asm volatile("st.shared.u32 [%0], %1;" :: "r"(ad), "r"(0));
    }
    if (tid == 0){
        #pragma unroll
        for (int s = 0; s < 4; s++){ mbinit(FULLB + s*8, NTHR); mbinit(EMPTB + s*8, NTHR); }
    }
    __syncthreads();

    // ---- loader precompute ----
    uint32_t a_rs[5];
    #pragma unroll
    for (int j = 0; j < 5; j++){
        int o = tid + j*NTHR;
        int row = o/18, seg = o - row*18;
        a_rs[j] = ((uint32_t)row << 8) | (uint32_t)seg;
    }
    uint32_t b_ps[3];
    #pragma unroll
    for (int j = 0; j < 3; j++){
        int o = tid + j*NTHR;
        if (o >= 640) o = 0;
        int pr = o/80, rem = o - pr*80, slot = rem >> 3, seg = rem & 7;
        b_ps[j] = ((uint32_t)pr << 16) | ((uint32_t)slot << 8) | (uint32_t)seg;
    }

    int ntile = 0;
    for (int t = cta; t < NTILE; t += NCTA) ntile++;
    const int tot = ntile*16;

    auto LOAD = [&](int gl){
        const int c = gl & 15;
        const int tile = cta + (gl >> 4)*NCTA;
        const int img = tile >> 4, by = (tile >> 2) & 3, bx = tile & 3;
        const int co0 = by*64;
        uint32_t s = sb + (uint32_t)((gl & 3)*STAGE);
        #pragma unroll
        for (int j = 0; j < 5; j++){
            if (j < 4 || tid < 128){
                uint32_t row = a_rs[j] >> 8, seg = a_rs[j] & 255u;
                cp16(s + row*304 + seg*16, Wt + (co0 + row)*2304 + seg*8 + c*144);
            }
        }
        #pragma unroll
        for (int j = 0; j < 3; j++){
            if (j < 2 || tid < 128){         // 256+256+128 = 640 ops exactly
                uint32_t pr = b_ps[j] >> 16, slot = (b_ps[j] >> 8) & 255u, seg = b_ps[j] & 255u;
                int gr = bx*8 + (int)slot - 1;
                int ok = ((unsigned)gr < 32u) ? 1 : 0;
                uint32_t dst = s + OFF_BST + pr*1760 + slot*176 + 32 + seg*16;
                const __half2* src = Bsrc + ((size_t)(img*128 + c*8 + pr)*1024
                                             + (ok ? gr : 0)*32 + seg*4);
                cp16z(dst, src, ok);
            }
        }
        cp_arrive(FULLB + (uint32_t)((gl & 3)*8));   // arrive when this thread's copies land
    };

    float acc[4][4][4];
    #pragma unroll
    for (int i=0;i<4;i++)
        #pragma unroll
        for (int j=0;j<4;j++)
            #pragma unroll
            for (int r=0;r<4;r++) acc[i][j][r] = 0.0f;

    LOAD(0); LOAD(1); LOAD(2);

    #pragma unroll 1
    for (int gl = 0; gl < tot; gl++){
        const int st = gl & 3;
        mwait(FULLB + st*8, (gl >> 2) & 1);          // per-warp: stage ready

        const uint32_t sA = sb + (uint32_t)(st*STAGE);
        const uint32_t sB = sA + OFF_BST;
        #pragma unroll
        for (int off = 0; off < 9; off++){
            const int dh = off/3, dw = off - 3*(off/3);
            uint32_t a[4][4];
            #pragma unroll
            for (int mt = 0; mt < 4; mt++){
                uint32_t ad = sA + (uint32_t)((mt*16 + (lane & 15))*304
                                              + off*32 + ((lane >> 4) << 4));
                ldsm4(a[mt], ad);
            }
            uint32_t b[4][2];
            #pragma unroll
            for (int nt = 0; nt < 4; nt++){
                uint32_t ad = sB + (uint32_t)((qt*440 + (wn + dh)*44
                                               + 7 + nt*8 + dw + qg)*4);
                b[nt][0] = lds32(ad);
                b[nt][1] = lds32(ad + 7040);     // cpair qt+4
            }
            #pragma unroll
            for (int mt = 0; mt < 4; mt++)
                #pragma unroll
                for (int nt = 0; nt < 4; nt++)
                    mma16(acc[mt][nt], a[mt], b[nt]);
        }
        mbarrive(EMPTB + st*8);                      // this thread done reading stage

        // ---- tile finished: fused epilogue (per-warp staging smem) ----
        if ((gl & 15) == 15){
            const int tile = cta + (gl >> 4)*NCTA;
            const int img = tile >> 4, by = (tile >> 2) & 3, bx = tile & 3;
            const int co0 = by*64;
            if (MODE == 0){
                char* Sw = smem + OFF_STG + warp*5120;   // [64 rows][40 halves]
                #pragma unroll
                for (int mt = 0; mt < 4; mt++){
                    const int co = co0 + mt*16 + qg;
                    const float i0 = g_inv[0][co],   s0 = g_bias[0][co];
                    const float i1 = g_inv[0][co+8], s1 = g_bias[0][co+8];
                    #pragma unroll
                    for (int nt = 0; nt < 4; nt++){
                        const int pxl = nt*8 + 2*qt;
                        float v0 = fmaxf(fmaf(acc[mt][nt][0], i0, s0), 0.f);
                        float v1 = fmaxf(fmaf(acc[mt][nt][1], i0, s0), 0.f);
                        float v2 = fmaxf(fmaf(acc[mt][nt][2], i1, s1), 0.f);
                        float v3 = fmaxf(fmaf(acc[mt][nt][3], i1, s1), 0.f);
                        *(uint32_t*)(Sw + ((mt*16 + qg    )*40 + pxl)*2) = pack_h2(v0, v1);
                        *(uint32_t*)(Sw + ((mt*16 + qg + 8)*40 + pxl)*2) = pack_h2(v2, v3);
                    }
                }
                __syncwarp();
                #pragma unroll
                for (int it = 0; it < 8; it++){
                    const int cpl = it*4 + (lane >> 3), px4 = lane & 7;
                    uint2 lo = *(uint2*)(Sw + ((2*cpl    )*40 + px4*4)*2);
                    uint2 hi = *(uint2*)(Sw + ((2*cpl + 1)*40 + px4*4)*2);
                    uint4 v;
                    v.x = __byte_perm(lo.x, hi.x, 0x5410);
                    v.y = __byte_perm(lo.x, hi.x, 0x7632);
                    v.z = __byte_perm(lo.y, hi.y, 0x5410);
                    v.w = __byte_perm(lo.y, hi.y, 0x7632);
                    size_t idx = ((size_t)(img*128 + by*32 + cpl))*1024
                               + bx*256 + wn*32 + px4*4;
                    *(uint4*)((uint32_t*)g_h16 + idx) = v;
                }
                __syncwarp();
            } else {
                #pragma unroll
                for (int mt = 0; mt < 4; mt++){
                    const int co = co0 + mt*16 + qg;
                    const float i0 = g_inv[1][co],   s0 = g_bias[1][co];
                    const float i1 = g_inv[1][co+8], s1 = g_bias[1][co+8];
                    #pragma unroll
                    for (int nt = 0; nt < 4; nt++){
                        const int p = bx*256 + wn*32 + nt*8 + 2*qt;
                        const size_t o0 = ((size_t)(img*256 + co))*1024 + p;
                        const size_t o1 = o0 + 8*1024;
                        const float2 r0 = *(const float2*)(resid + o0);
                        const float2 r1 = *(const float2*)(resid + o1);
                        float2 w0, w1;
                        w0.x = fmaxf(fmaf(acc[mt][nt][0], i0, s0) + r0.x, 0.f);
                        w0.y = fmaxf(fmaf(acc[mt][nt][1], i0, s0) + r0.y, 0.f);
                        w1.x = fmaxf(fmaf(acc[mt][nt][2], i1, s1) + r1.x, 0.f);
                        w1.y = fmaxf(fmaf(acc[mt][nt][3], i1, s1) + r1.y, 0.f);
                        *(float2*)(dout + o0) = w0;
                        *(float2*)(dout + o1) = w1;
                    }
                }
            }
            #pragma unroll
            for (int i=0;i<4;i++)
                #pragma unroll
                for (int j=0;j<4;j++)
                    #pragma unroll
                    for (int r=0;r<4;r++) acc[i][j][r] = 0.0f;
        }

        // ---- produce stage gl+3 (max slack on empty-wait; copies have 2+ chunks) ----
        if (gl + 3 < tot){
            const int d = (gl + 3) & 3;
            if (gl >= 1) mwait(EMPTB + d*8, ((gl - 1) >> 2) & 1);
            LOAD(gl + 3);
        }
    }
}

extern "C" void kernel_launch(void* const* d_in, const int* in_sizes, int n_in,
                              void* d_out, int out_size){
    const float* x   = (const float*)d_in[0];
    const float* w1  = (const float*)d_in[1];
    const float* g1  = (const float*)d_in[2];
    const float* b1  = (const float*)d_in[3];
    const float* rm1 = (const float*)d_in[4];
    const float* rv1 = (const float*)d_in[5];
    const float* w2  = (const float*)d_in[6];
    const float* g2  = (const float*)d_in[7];
    const float* b2  = (const float*)d_in[8];
    const float* rm2 = (const float*)d_in[9];
    const float* rv2 = (const float*)d_in[10];
    float* out = (float*)d_out;

    prep_kernel<<<2304, 256>>>(w1, w2, g1,b1,rm1,rv1, g2,b2,rm2,rv2);
    pack_x_kernel<<<8192, 256>>>((const float4*)x);

    cudaFuncSetAttribute(conv_f16<0>, cudaFuncAttributeMaxDynamicSharedMemorySize, SMEM_BYTES);
    cudaFuncSetAttribute(conv_f16<1>, cudaFuncAttributeMaxDynamicSharedMemorySize, SMEM_BYTES);
    conv_f16<0><<<NCTA, NTHR, SMEM_BYTES>>>(nullptr, nullptr);
    conv_f16<1><<<NCTA, NTHR, SMEM_BYTES>>>(x, out);
}